// round 6
// baseline (speedup 1.0000x reference)
#include <cuda_runtime.h>
#include <cuda_bf16.h>
#include <math.h>
#include <stdint.h>

// Problem constants
#define DIMD   1536
#define HEADS  12
#define HD     128
#define LSEQ   3520
#define EPS_V  1e-6f
#define SCALE_V 0.08838834764831845f   // 1/sqrt(128)

// ---------------------------------------------------------------------------
// Scratch (device globals: allocation-free, graph-safe)
// ---------------------------------------------------------------------------
__device__ float g_q[(size_t)LSEQ * DIMD];
__device__ float g_k[(size_t)LSEQ * DIMD];
__device__ float g_v[(size_t)LSEQ * DIMD];
__device__ float g_attn[(size_t)LSEQ * DIMD];
__device__ __nv_bfloat16 g_xhi[(size_t)LSEQ * DIMD];
__device__ __nv_bfloat16 g_xlo[(size_t)LSEQ * DIMD];
__device__ __nv_bfloat16 g_whi[(size_t)4 * DIMD * DIMD];
__device__ __nv_bfloat16 g_wlo[(size_t)4 * DIMD * DIMD];

// ---------------------------------------------------------------------------
// fp32 -> bf16 hi/lo split:  x = hi + lo + O(2^-16 x)
// ---------------------------------------------------------------------------
__global__ __launch_bounds__(256) void split_bf16(
    const float* __restrict__ src,
    __nv_bfloat16* __restrict__ hi, __nv_bfloat16* __restrict__ lo, int n4)
{
    int i = blockIdx.x * 256 + threadIdx.x;
    if (i >= n4) return;
    float4 v = ((const float4*)src)[i];
    __nv_bfloat16 h0 = __float2bfloat16_rn(v.x);
    __nv_bfloat16 h1 = __float2bfloat16_rn(v.y);
    __nv_bfloat16 h2 = __float2bfloat16_rn(v.z);
    __nv_bfloat16 h3 = __float2bfloat16_rn(v.w);
    __nv_bfloat16 l0 = __float2bfloat16_rn(v.x - __bfloat162float(h0));
    __nv_bfloat16 l1 = __float2bfloat16_rn(v.y - __bfloat162float(h1));
    __nv_bfloat16 l2 = __float2bfloat16_rn(v.z - __bfloat162float(h2));
    __nv_bfloat16 l3 = __float2bfloat16_rn(v.w - __bfloat162float(h3));
    __nv_bfloat162* hp = (__nv_bfloat162*)hi;
    __nv_bfloat162* lp = (__nv_bfloat162*)lo;
    __nv_bfloat162 a; a.x = h0; a.y = h1;
    __nv_bfloat162 b; b.x = h2; b.y = h3;
    hp[2 * i] = a; hp[2 * i + 1] = b;
    a.x = l0; a.y = l1; b.x = l2; b.y = l3;
    lp[2 * i] = a; lp[2 * i + 1] = b;
}

// ---------------------------------------------------------------------------
// Tensor-core GEMM (NT): C[m,n] = sum_k A[m,k]*W[n,k] + bias[n]
// A,W given as bf16 hi/lo pairs; product = hh + hl + lh (fp32 accum).
// Tiles: BM=BN=128, BK=32. 256 threads = 8 warps (2 m x 4 n), warp = 64x32.
// blockIdx.z selects among packed weights / biases / outputs (fused QKV).
// ---------------------------------------------------------------------------
#define TBM 128
#define TBN 128
#define TBK 32
#define SAS 40   // smem row stride in bf16 (80B; 16B-aligned rows, ldsm-conflict-free)

__device__ __forceinline__ void ldsm4(uint32_t& r0, uint32_t& r1,
                                      uint32_t& r2, uint32_t& r3, uint32_t addr)
{
    asm volatile("ldmatrix.sync.aligned.m8n8.x4.shared.b16 {%0,%1,%2,%3}, [%4];"
                 : "=r"(r0), "=r"(r1), "=r"(r2), "=r"(r3) : "r"(addr));
}

__device__ __forceinline__ void mma_bf16(float c[4], const uint32_t a[4],
                                         const uint32_t b[2])
{
    asm volatile(
        "mma.sync.aligned.m16n8k16.row.col.f32.bf16.bf16.f32 "
        "{%0,%1,%2,%3}, {%4,%5,%6,%7}, {%8,%9}, {%0,%1,%2,%3};"
        : "+f"(c[0]), "+f"(c[1]), "+f"(c[2]), "+f"(c[3])
        : "r"(a[0]), "r"(a[1]), "r"(a[2]), "r"(a[3]), "r"(b[0]), "r"(b[1]));
}

__global__ __launch_bounds__(256) void gemm_bf16s(
    const __nv_bfloat16* __restrict__ Ahi, const __nv_bfloat16* __restrict__ Alo,
    const __nv_bfloat16* __restrict__ Wh,  const __nv_bfloat16* __restrict__ Wl,
    const float* __restrict__ bias0, const float* __restrict__ bias1,
    const float* __restrict__ bias2,
    float* __restrict__ C0, float* __restrict__ C1, float* __restrict__ C2,
    int M, int N, int K)
{
    const int z = blockIdx.z;
    const __nv_bfloat16* Bh = Wh + (size_t)z * N * K;
    const __nv_bfloat16* Bl = Wl + (size_t)z * N * K;
    const float* bias = (z == 0) ? bias0 : ((z == 1) ? bias1 : bias2);
    float*       C    = (z == 0) ? C0    : ((z == 1) ? C1    : C2);

    __shared__ __align__(16) __nv_bfloat16 sAh[TBM][SAS];
    __shared__ __align__(16) __nv_bfloat16 sAl[TBM][SAS];
    __shared__ __align__(16) __nv_bfloat16 sBh[TBN][SAS];
    __shared__ __align__(16) __nv_bfloat16 sBl[TBN][SAS];

    const int tid = threadIdx.x;
    const int lane = tid & 31;
    const int wid = tid >> 5;
    const int wm = wid >> 2;          // 0..1
    const int wn = wid & 3;           // 0..3
    const int m0 = blockIdx.y * TBM;
    const int n0 = blockIdx.x * TBN;

    float c[4][4][4];
#pragma unroll
    for (int mf = 0; mf < 4; mf++)
#pragma unroll
        for (int nf = 0; nf < 4; nf++)
#pragma unroll
            for (int e = 0; e < 4; e++) c[mf][nf][e] = 0.f;

    // ldmatrix lane->address decomposition (s = lane>>3, r = lane&7)
    const int lr  = lane & 7;
    const int a_ro = lr + ((lane >> 3) & 1) * 8;   // A: s&1 -> +8 rows
    const int a_co = (lane >> 4) * 8;              // A: s>>1 -> +8 cols(k)
    const int b_ro = lr + (lane >> 4) * 8;         // B: s>>1 -> +8 rows(n)
    const int b_co = ((lane >> 3) & 1) * 8;        // B: s&1 -> +8 cols(k)

    for (int k0 = 0; k0 < K; k0 += TBK) {
        // ---- load tiles (each thread: 2 x uint4 per array) ----
#pragma unroll
        for (int i = 0; i < 2; i++) {
            int idx = tid * 2 + i;            // 0..511
            int row = idx >> 2;
            int q = (idx & 3) * 8;            // bf16 offset within 32-k chunk
            int ga = m0 + row; if (ga > M - 1) ga = M - 1;
            *(uint4*)&sAh[row][q] = *(const uint4*)&Ahi[(size_t)ga * K + k0 + q];
            *(uint4*)&sAl[row][q] = *(const uint4*)&Alo[(size_t)ga * K + k0 + q];
            *(uint4*)&sBh[row][q] = *(const uint4*)&Bh[(size_t)(n0 + row) * K + k0 + q];
            *(uint4*)&sBl[row][q] = *(const uint4*)&Bl[(size_t)(n0 + row) * K + k0 + q];
        }
        __syncthreads();

#pragma unroll
        for (int ks = 0; ks < 2; ks++) {
            const int kk = ks * 16;
            uint32_t ah[4][4], al[4][4], bh[4][2], bl[4][2];
#pragma unroll
            for (int mf = 0; mf < 4; mf++) {
                int row = wm * 64 + mf * 16 + a_ro;
                int col = kk + a_co;
                ldsm4(ah[mf][0], ah[mf][1], ah[mf][2], ah[mf][3],
                      (uint32_t)__cvta_generic_to_shared(&sAh[row][col]));
                ldsm4(al[mf][0], al[mf][1], al[mf][2], al[mf][3],
                      (uint32_t)__cvta_generic_to_shared(&sAl[row][col]));
            }
#pragma unroll
            for (int p = 0; p < 2; p++) {
                int row = wn * 32 + p * 16 + b_ro;
                int col = kk + b_co;
                uint32_t r0, r1, r2, r3;
                ldsm4(r0, r1, r2, r3,
                      (uint32_t)__cvta_generic_to_shared(&sBh[row][col]));
                bh[2 * p][0] = r0; bh[2 * p][1] = r1;
                bh[2 * p + 1][0] = r2; bh[2 * p + 1][1] = r3;
                ldsm4(r0, r1, r2, r3,
                      (uint32_t)__cvta_generic_to_shared(&sBl[row][col]));
                bl[2 * p][0] = r0; bl[2 * p][1] = r1;
                bl[2 * p + 1][0] = r2; bl[2 * p + 1][1] = r3;
            }
#pragma unroll
            for (int mf = 0; mf < 4; mf++)
#pragma unroll
                for (int nf = 0; nf < 4; nf++) {
                    mma_bf16(c[mf][nf], ah[mf], bh[nf]);   // hi*hi
                    mma_bf16(c[mf][nf], ah[mf], bl[nf]);   // hi*lo
                    mma_bf16(c[mf][nf], al[mf], bh[nf]);   // lo*hi
                }
        }
        __syncthreads();
    }

    // ---- epilogue ----
    const int gid = lane >> 2;        // 0..7
    const int tig = lane & 3;         // 0..3
#pragma unroll
    for (int mf = 0; mf < 4; mf++) {
#pragma unroll
        for (int nf = 0; nf < 4; nf++) {
            int m = m0 + wm * 64 + mf * 16 + gid;
            int n = n0 + wn * 32 + nf * 8 + tig * 2;
            float2 bv2 = make_float2(bias[n], bias[n + 1]);
            if (m < M) {
                float2 o; o.x = c[mf][nf][0] + bv2.x; o.y = c[mf][nf][1] + bv2.y;
                *(float2*)&C[(size_t)m * N + n] = o;
            }
            if (m + 8 < M) {
                float2 o; o.x = c[mf][nf][2] + bv2.x; o.y = c[mf][nf][3] + bv2.y;
                *(float2*)&C[(size_t)(m + 8) * N + n] = o;
            }
        }
    }
}

// ---------------------------------------------------------------------------
// Fused RMSNorm (over DIM) + RoPE (per head, pair-interleaved) in-place.
// blockIdx.x = row, blockIdx.y = 0 (q, scaled by SCALE) / 1 (k)
// ---------------------------------------------------------------------------
__global__ __launch_bounds__(256) void rmsnorm_rope(
    float* __restrict__ qbuf, float* __restrict__ kbuf,
    const float* __restrict__ gq, const float* __restrict__ gk,
    const float* __restrict__ freqs, const int* __restrict__ grid_sizes)
{
    const int row = blockIdx.x;
    float* buf = (blockIdx.y == 0) ? qbuf : kbuf;
    const float* g = (blockIdx.y == 0) ? gq : gk;
    const float outscale = (blockIdx.y == 0) ? SCALE_V : 1.0f;

    float* rp = buf + (size_t)row * DIMD;
    const int tid = threadIdx.x;

    float local = 0.f;
    for (int i = tid; i < DIMD; i += 256) {
        float v = rp[i];
        local = fmaf(v, v, local);
    }
#pragma unroll
    for (int d = 16; d >= 1; d >>= 1)
        local += __shfl_xor_sync(0xffffffffu, local, d);

    __shared__ float red[8];
    __shared__ float s_rn;
    if ((tid & 31) == 0) red[tid >> 5] = local;
    __syncthreads();
    if (tid == 0) {
        float t = 0.f;
        for (int w = 0; w < 8; w++) t += red[w];
        s_rn = rsqrtf(t / (float)DIMD + EPS_V);
    }
    __syncthreads();
    const float rn = s_rn;

    const int hh = grid_sizes[1], ww = grid_sizes[2];
    const int fi = row / (hh * ww);
    const int hi = (row / ww) % hh;
    const int wi = row % ww;

    for (int p = tid; p < DIMD / 2; p += 256) {
        const int head = p >> 6;
        const int j = p & 63;
        const int fr = (j < 22) ? fi : ((j < 43) ? hi : wi);
        const float ang = freqs[fr * 64 + j];
        const float sn = sinf(ang);
        const float cs = cosf(ang);
        const int e = (head << 7) + (j << 1);
        const float x0 = rp[e]     * rn * g[e];
        const float x1 = rp[e + 1] * rn * g[e + 1];
        rp[e]     = (x0 * cs - x1 * sn) * outscale;
        rp[e + 1] = (x0 * sn + x1 * cs) * outscale;
    }
}

// ---------------------------------------------------------------------------
// Flash attention, fp32. BLOCK_M=64, BLOCK_N=64, HD=128. 256 threads.
// Q pre-scaled by SCALE. Thread (rg = tid>>3, tc = tid&7):
//   rows owned:  r0 = 2*rg .. +1
//   S cols owned: n = tc + 8c           (shfl reduction in groups of 8 lanes)
//   O cols owned: d = tc*16 + i (contiguous strip -> float4 LDS/STG)
// ---------------------------------------------------------------------------
#define FBM 64
#define FBN 64
#define QSTR 132
#define PSTR 68
#define FLASH_SMEM ((3 * 64 * QSTR + 64 * PSTR) * 4)

extern __shared__ float fsm[];

__global__ __launch_bounds__(256) void flash_kernel(
    const float* __restrict__ Q, const float* __restrict__ Kmat,
    const float* __restrict__ V, float* __restrict__ O, int nkb)
{
    const int head = blockIdx.y;
    const int m0 = blockIdx.x * FBM;

    float* Qs = fsm;
    float* Ks = Qs + 64 * QSTR;
    float* Vs = Ks + 64 * QSTR;
    float* Ps = Vs + 64 * QSTR;

    const int tid = threadIdx.x;
    const int tc  = tid & 7;
    const int rg  = tid >> 3;
    const int r0  = rg * 2;
    const int rot = rg & 3;

    {
        const float* qb = Q + (size_t)m0 * DIMD + head * HD;
#pragma unroll
        for (int it = 0; it < 8; it++) {
            int idx = it * 256 + tid;
            int row = idx >> 5, c4 = idx & 31;
            *(float4*)(&Qs[row * QSTR + c4 * 4]) =
                *(const float4*)(qb + (size_t)row * DIMD + c4 * 4);
        }
    }
    __syncthreads();

    float O_[2][16];
    float m_[2], l_[2];
#pragma unroll
    for (int r = 0; r < 2; r++) {
        m_[r] = -1e30f;
        l_[r] = 0.f;
#pragma unroll
        for (int i = 0; i < 16; i++) O_[r][i] = 0.f;
    }

    for (int nb = 0; nb < nkb; nb++) {
        const int n0 = nb * FBN;
        __syncthreads();

        const float* kb = Kmat + (size_t)n0 * DIMD + head * HD;
        const float* vb = V    + (size_t)n0 * DIMD + head * HD;
#pragma unroll
        for (int it = 0; it < 8; it++) {
            int idx = it * 256 + tid;
            int row = idx >> 5, c4 = idx & 31;
            *(float4*)(&Ks[row * QSTR + c4 * 4]) =
                *(const float4*)(kb + (size_t)row * DIMD + c4 * 4);
            *(float4*)(&Vs[row * QSTR + c4 * 4]) =
                *(const float4*)(vb + (size_t)row * DIMD + c4 * 4);
        }
        __syncthreads();

        float s[2][8];
#pragma unroll
        for (int r = 0; r < 2; r++)
#pragma unroll
            for (int c = 0; c < 8; c++) s[r][c] = 0.f;

#pragma unroll 4
        for (int k4 = 0; k4 < HD / 4; k4++) {
            const float4 q0 = *(const float4*)(&Qs[(r0 + 0) * QSTR + k4 * 4]);
            const float4 q1 = *(const float4*)(&Qs[(r0 + 1) * QSTR + k4 * 4]);
#pragma unroll
            for (int c = 0; c < 8; c++) {
                const float4 kv = *(const float4*)(&Ks[(tc + 8 * c) * QSTR + k4 * 4]);
                s[0][c] = fmaf(q0.x, kv.x, fmaf(q0.y, kv.y,
                          fmaf(q0.z, kv.z, fmaf(q0.w, kv.w, s[0][c]))));
                s[1][c] = fmaf(q1.x, kv.x, fmaf(q1.y, kv.y,
                          fmaf(q1.z, kv.z, fmaf(q1.w, kv.w, s[1][c]))));
            }
        }

#pragma unroll
        for (int r = 0; r < 2; r++) {
            float mx = s[r][0];
#pragma unroll
            for (int c = 1; c < 8; c++) mx = fmaxf(mx, s[r][c]);
            mx = fmaxf(mx, __shfl_xor_sync(0xffffffffu, mx, 1, 8));
            mx = fmaxf(mx, __shfl_xor_sync(0xffffffffu, mx, 2, 8));
            mx = fmaxf(mx, __shfl_xor_sync(0xffffffffu, mx, 4, 8));
            const float mn = fmaxf(m_[r], mx);
            const float alpha = __expf(m_[r] - mn);
            m_[r] = mn;
            float sum = 0.f;
#pragma unroll
            for (int c = 0; c < 8; c++) {
                float pe = __expf(s[r][c] - mn);
                s[r][c] = pe;
                sum += pe;
            }
            sum += __shfl_xor_sync(0xffffffffu, sum, 1, 8);
            sum += __shfl_xor_sync(0xffffffffu, sum, 2, 8);
            sum += __shfl_xor_sync(0xffffffffu, sum, 4, 8);
            l_[r] = l_[r] * alpha + sum;
#pragma unroll
            for (int i = 0; i < 16; i++) O_[r][i] *= alpha;
#pragma unroll
            for (int c = 0; c < 8; c++)
                Ps[(r0 + r) * PSTR + tc + 8 * c] = s[r][c];
        }
        __syncthreads();

#pragma unroll 2
        for (int n4 = 0; n4 < FBN / 4; n4++) {
            const float4 p0 = *(const float4*)(&Ps[(r0 + 0) * PSTR + n4 * 4]);
            const float4 p1 = *(const float4*)(&Ps[(r0 + 1) * PSTR + n4 * 4]);
            const float pr0[4] = {p0.x, p0.y, p0.z, p0.w};
            const float pr1[4] = {p1.x, p1.y, p1.z, p1.w};
#pragma unroll
            for (int nn = 0; nn < 4; nn++) {
                const float* vrow = &Vs[(n4 * 4 + nn) * QSTR + tc * 16];
#pragma unroll
                for (int u = 0; u < 4; u++) {
                    const int uu = (u + rot) & 3;
                    const float4 vv = *(const float4*)(&vrow[uu * 4]);
                    O_[0][uu * 4 + 0] = fmaf(pr0[nn], vv.x, O_[0][uu * 4 + 0]);
                    O_[0][uu * 4 + 1] = fmaf(pr0[nn], vv.y, O_[0][uu * 4 + 1]);
                    O_[0][uu * 4 + 2] = fmaf(pr0[nn], vv.z, O_[0][uu * 4 + 2]);
                    O_[0][uu * 4 + 3] = fmaf(pr0[nn], vv.w, O_[0][uu * 4 + 3]);
                    O_[1][uu * 4 + 0] = fmaf(pr1[nn], vv.x, O_[1][uu * 4 + 0]);
                    O_[1][uu * 4 + 1] = fmaf(pr1[nn], vv.y, O_[1][uu * 4 + 1]);
                    O_[1][uu * 4 + 2] = fmaf(pr1[nn], vv.z, O_[1][uu * 4 + 2]);
                    O_[1][uu * 4 + 3] = fmaf(pr1[nn], vv.w, O_[1][uu * 4 + 3]);
                }
            }
        }
    }

#pragma unroll
    for (int r = 0; r < 2; r++) {
        const float inv = 1.0f / l_[r];
        float* orow = O + (size_t)(m0 + r0 + r) * DIMD + head * HD + tc * 16;
#pragma unroll
        for (int u = 0; u < 4; u++) {
            float4 o4;
            o4.x = O_[r][u * 4 + 0] * inv;
            o4.y = O_[r][u * 4 + 1] * inv;
            o4.z = O_[r][u * 4 + 2] * inv;
            o4.w = O_[r][u * 4 + 3] * inv;
            *(float4*)(&orow[u * 4]) = o4;
        }
    }
}

// ---------------------------------------------------------------------------
// Launch
// ---------------------------------------------------------------------------
extern "C" void kernel_launch(void* const* d_in, const int* in_sizes, int n_in,
                              void* d_out, int out_size)
{
    const float* x          = (const float*)d_in[0];
    const int*   grid_sizes = (const int*)  d_in[2];
    const float* freqs      = (const float*)d_in[3];
    const float* Wq = (const float*)d_in[4];
    const float* bq = (const float*)d_in[5];
    const float* Wk = (const float*)d_in[6];
    const float* bk = (const float*)d_in[7];
    const float* Wv = (const float*)d_in[8];
    const float* bv = (const float*)d_in[9];
    const float* Wo = (const float*)d_in[10];
    const float* bo = (const float*)d_in[11];
    const float* gq = (const float*)d_in[12];
    const float* gk = (const float*)d_in[13];
    float* out = (float*)d_out;

    float *q, *k, *v, *attn;
    __nv_bfloat16 *xhi, *xlo, *whi, *wlo;
    cudaGetSymbolAddress((void**)&q,    g_q);
    cudaGetSymbolAddress((void**)&k,    g_k);
    cudaGetSymbolAddress((void**)&v,    g_v);
    cudaGetSymbolAddress((void**)&attn, g_attn);
    cudaGetSymbolAddress((void**)&xhi,  g_xhi);
    cudaGetSymbolAddress((void**)&xlo,  g_xlo);
    cudaGetSymbolAddress((void**)&whi,  g_whi);
    cudaGetSymbolAddress((void**)&wlo,  g_wlo);

    const int nx4 = LSEQ * DIMD / 4;          // 1351680
    const int nw4 = DIMD * DIMD / 4;          // 589824
    const size_t woff = (size_t)DIMD * DIMD;  // elems per weight

    // Split inputs to bf16 hi/lo
    split_bf16<<<(nx4 + 255) / 256, 256>>>(x, xhi, xlo, nx4);
    split_bf16<<<(nw4 + 255) / 256, 256>>>(Wq, whi + 0 * woff, wlo + 0 * woff, nw4);
    split_bf16<<<(nw4 + 255) / 256, 256>>>(Wk, whi + 1 * woff, wlo + 1 * woff, nw4);
    split_bf16<<<(nw4 + 255) / 256, 256>>>(Wv, whi + 2 * woff, wlo + 2 * woff, nw4);
    split_bf16<<<(nw4 + 255) / 256, 256>>>(Wo, whi + 3 * woff, wlo + 3 * woff, nw4);

    // QKV projections (fused, tensor cores)
    const dim3 gqkv(DIMD / TBN, (LSEQ + TBM - 1) / TBM, 3);  // (12, 28, 3)
    gemm_bf16s<<<gqkv, 256>>>(xhi, xlo, whi, wlo, bq, bk, bv, q, k, v,
                              LSEQ, DIMD, DIMD);

    rmsnorm_rope<<<dim3(LSEQ, 2), 256>>>(q, k, gq, gk, freqs, grid_sizes);

    cudaFuncSetAttribute(flash_kernel,
                         cudaFuncAttributeMaxDynamicSharedMemorySize,
                         FLASH_SMEM);
    flash_kernel<<<dim3(LSEQ / FBM, HEADS), 256, FLASH_SMEM>>>(
        q, k, v, attn, LSEQ / FBN);

    // Output projection (split attn, reuse x buffers)
    split_bf16<<<(nx4 + 255) / 256, 256>>>(attn, xhi, xlo, nx4);
    const dim3 go(DIMD / TBN, (LSEQ + TBM - 1) / TBM, 1);
    gemm_bf16s<<<go, 256>>>(xhi, xlo, whi + 3 * woff, wlo + 3 * woff,
                            bo, bo, bo, out, out, out, LSEQ, DIMD, DIMD);
}

// round 11
// speedup vs baseline: 1.9579x; 1.9579x over previous
#include <cuda_runtime.h>
#include <cuda_bf16.h>
#include <math.h>

// Problem constants
#define DIMD   1536
#define HEADS  12
#define HD     128
#define LSEQ   3520
#define EPS_V  1e-6f
#define SCALE_V 0.08838834764831845f   // 1/sqrt(128)

// ---------------------------------------------------------------------------
// Scratch (device globals: allocation-free, graph-safe)
// ---------------------------------------------------------------------------
__device__ float g_q[(size_t)LSEQ * DIMD];
__device__ float g_k[(size_t)LSEQ * DIMD];
__device__ float g_v[(size_t)LSEQ * DIMD];
__device__ float g_attn[(size_t)LSEQ * DIMD];

// ---------------------------------------------------------------------------
// GEMM (NT): C[m,n] = sum_k A[m,k]*B[n,k] + bias[n]
// A: (M,K) row-major, B: (N,K) row-major. BM=BN=128, BK=16, 256 thr, 8x8 micro
// blockIdx.z selects among up to 3 (B, bias, C) triples (fused QKV).
// ---------------------------------------------------------------------------
#define GBM 128
#define GBN 128
#define GBK 16

__global__ __launch_bounds__(256) void gemm_nt3(
    const float* __restrict__ A,
    const float* __restrict__ B0, const float* __restrict__ B1,
    const float* __restrict__ B2,
    const float* __restrict__ bias0, const float* __restrict__ bias1,
    const float* __restrict__ bias2,
    float* __restrict__ C0, float* __restrict__ C1, float* __restrict__ C2,
    int M, int N, int K)
{
    const int z = blockIdx.z;
    const float* B    = (z == 0) ? B0    : ((z == 1) ? B1    : B2);
    const float* bias = (z == 0) ? bias0 : ((z == 1) ? bias1 : bias2);
    float*       C    = (z == 0) ? C0    : ((z == 1) ? C1    : C2);

    __shared__ float As[GBK][GBM];
    __shared__ float Bs[GBK][GBN];

    const int tid = threadIdx.x;
    const int m0 = blockIdx.y * GBM;
    const int n0 = blockIdx.x * GBN;
    const int tr = tid >> 4;   // 0..15
    const int tc = tid & 15;   // 0..15

    float acc[8][8];
#pragma unroll
    for (int i = 0; i < 8; i++)
#pragma unroll
        for (int j = 0; j < 8; j++) acc[i][j] = 0.f;

    for (int k0 = 0; k0 < K; k0 += GBK) {
        // Load A tile (128x16) as float4, transposed into As[k][m]
#pragma unroll
        for (int j = 0; j < 2; j++) {
            int idx = tid * 2 + j;           // 0..511
            int row = idx >> 2, c4 = idx & 3;
            float4 v = make_float4(0.f, 0.f, 0.f, 0.f);
            if (m0 + row < M)
                v = *(const float4*)(A + (size_t)(m0 + row) * K + k0 + c4 * 4);
            As[c4 * 4 + 0][row] = v.x;
            As[c4 * 4 + 1][row] = v.y;
            As[c4 * 4 + 2][row] = v.z;
            As[c4 * 4 + 3][row] = v.w;
        }
        // Load B tile (128x16): N is a multiple of 128 here
#pragma unroll
        for (int j = 0; j < 2; j++) {
            int idx = tid * 2 + j;
            int row = idx >> 2, c4 = idx & 3;
            float4 v = *(const float4*)(B + (size_t)(n0 + row) * K + k0 + c4 * 4);
            Bs[c4 * 4 + 0][row] = v.x;
            Bs[c4 * 4 + 1][row] = v.y;
            Bs[c4 * 4 + 2][row] = v.z;
            Bs[c4 * 4 + 3][row] = v.w;
        }
        __syncthreads();

#pragma unroll
        for (int kk = 0; kk < GBK; kk++) {
            float a[8], b[8];
            *(float4*)(a + 0) = *(const float4*)(&As[kk][tr * 8 + 0]);
            *(float4*)(a + 4) = *(const float4*)(&As[kk][tr * 8 + 4]);
            *(float4*)(b + 0) = *(const float4*)(&Bs[kk][tc * 8 + 0]);
            *(float4*)(b + 4) = *(const float4*)(&Bs[kk][tc * 8 + 4]);
#pragma unroll
            for (int i = 0; i < 8; i++)
#pragma unroll
                for (int j = 0; j < 8; j++)
                    acc[i][j] = fmaf(a[i], b[j], acc[i][j]);
        }
        __syncthreads();
    }

    // Epilogue
#pragma unroll
    for (int i = 0; i < 8; i++) {
        int row = m0 + tr * 8 + i;
        if (row >= M) break;
#pragma unroll
        for (int j = 0; j < 8; j++) {
            int col = n0 + tc * 8 + j;
            C[(size_t)row * N + col] = acc[i][j] + bias[col];
        }
    }
}

// ---------------------------------------------------------------------------
// Fused RMSNorm (over DIM) + RoPE (per head, pair-interleaved) in-place.
// blockIdx.x + row0 = row, blockIdx.y = 0 (q, scaled by SCALE) / 1 (k)
// (row-chunked into 3 launches purely to position flash_kernel as the 5th
//  launch overall for the ncu -s 5 -c 1 window)
// ---------------------------------------------------------------------------
__global__ __launch_bounds__(256) void rmsnorm_rope(
    float* __restrict__ qbuf, float* __restrict__ kbuf,
    const float* __restrict__ gq, const float* __restrict__ gk,
    const float* __restrict__ freqs, const int* __restrict__ grid_sizes,
    int row0)
{
    const int row = row0 + blockIdx.x;
    float* buf = (blockIdx.y == 0) ? qbuf : kbuf;
    const float* g = (blockIdx.y == 0) ? gq : gk;
    const float outscale = (blockIdx.y == 0) ? SCALE_V : 1.0f;

    float* rp = buf + (size_t)row * DIMD;
    const int tid = threadIdx.x;

    float local = 0.f;
    for (int i = tid; i < DIMD; i += 256) {
        float v = rp[i];
        local = fmaf(v, v, local);
    }
#pragma unroll
    for (int d = 16; d >= 1; d >>= 1)
        local += __shfl_xor_sync(0xffffffffu, local, d);

    __shared__ float red[8];
    __shared__ float s_rn;
    if ((tid & 31) == 0) red[tid >> 5] = local;
    __syncthreads();
    if (tid == 0) {
        float t = 0.f;
        for (int w = 0; w < 8; w++) t += red[w];
        s_rn = rsqrtf(t / (float)DIMD + EPS_V);
    }
    __syncthreads();
    const float rn = s_rn;

    const int hh = grid_sizes[1], ww = grid_sizes[2];
    const int fi = row / (hh * ww);
    const int hi = (row / ww) % hh;
    const int wi = row % ww;

    for (int p = tid; p < DIMD / 2; p += 256) {
        const int head = p >> 6;
        const int j = p & 63;
        const int fr = (j < 22) ? fi : ((j < 43) ? hi : wi);
        const float ang = freqs[fr * 64 + j];
        const float sn = sinf(ang);
        const float cs = cosf(ang);
        const int e = (head << 7) + (j << 1);
        const float x0 = rp[e]     * rn * g[e];
        const float x1 = rp[e + 1] * rn * g[e + 1];
        rp[e]     = (x0 * cs - x1 * sn) * outscale;
        rp[e + 1] = (x0 * sn + x1 * cs) * outscale;
    }
}

// ---------------------------------------------------------------------------
// Flash attention, fp32. BLOCK_M=64, BLOCK_N=64, HD=128. 256 threads.
// Q pre-scaled by SCALE. Thread (rg = tid>>3, tc = tid&7):
//   rows owned:  r0 = 2*rg .. +1
//   S cols owned: n = tc + 8c           (shfl reduction in groups of 8 lanes)
//   O cols owned: d = tc*16 + i (contiguous strip -> float4 LDS/STG)
// V reads in the O-loop are rg-uniform -> full smem broadcast (1 crossbar
// phase per LDS.128); do NOT rotate the u-subloop (rotation makes rg-groups
// read distinct chunks and quadruples crossbar traffic).
// ---------------------------------------------------------------------------
#define FBM 64
#define FBN 64
#define QSTR 132
#define PSTR 68
#define FLASH_SMEM ((3 * 64 * QSTR + 64 * PSTR) * 4)

extern __shared__ float fsm[];

__global__ __launch_bounds__(256) void flash_kernel(
    const float* __restrict__ Q, const float* __restrict__ Kmat,
    const float* __restrict__ V, float* __restrict__ O, int nkb)
{
    const int head = blockIdx.y;
    const int m0 = blockIdx.x * FBM;

    float* Qs = fsm;
    float* Ks = Qs + 64 * QSTR;
    float* Vs = Ks + 64 * QSTR;
    float* Ps = Vs + 64 * QSTR;

    const int tid = threadIdx.x;
    const int tc  = tid & 7;
    const int rg  = tid >> 3;
    const int r0  = rg * 2;

    {
        const float* qb = Q + (size_t)m0 * DIMD + head * HD;
#pragma unroll
        for (int it = 0; it < 8; it++) {
            int idx = it * 256 + tid;
            int row = idx >> 5, c4 = idx & 31;
            *(float4*)(&Qs[row * QSTR + c4 * 4]) =
                *(const float4*)(qb + (size_t)row * DIMD + c4 * 4);
        }
    }
    __syncthreads();

    float O_[2][16];
    float m_[2], l_[2];
#pragma unroll
    for (int r = 0; r < 2; r++) {
        m_[r] = -1e30f;
        l_[r] = 0.f;
#pragma unroll
        for (int i = 0; i < 16; i++) O_[r][i] = 0.f;
    }

    for (int nb = 0; nb < nkb; nb++) {
        const int n0 = nb * FBN;
        __syncthreads();

        const float* kb = Kmat + (size_t)n0 * DIMD + head * HD;
        const float* vb = V    + (size_t)n0 * DIMD + head * HD;
#pragma unroll
        for (int it = 0; it < 8; it++) {
            int idx = it * 256 + tid;
            int row = idx >> 5, c4 = idx & 31;
            *(float4*)(&Ks[row * QSTR + c4 * 4]) =
                *(const float4*)(kb + (size_t)row * DIMD + c4 * 4);
            *(float4*)(&Vs[row * QSTR + c4 * 4]) =
                *(const float4*)(vb + (size_t)row * DIMD + c4 * 4);
        }
        __syncthreads();

        float s[2][8];
#pragma unroll
        for (int r = 0; r < 2; r++)
#pragma unroll
            for (int c = 0; c < 8; c++) s[r][c] = 0.f;

#pragma unroll 4
        for (int k4 = 0; k4 < HD / 4; k4++) {
            const float4 q0 = *(const float4*)(&Qs[(r0 + 0) * QSTR + k4 * 4]);
            const float4 q1 = *(const float4*)(&Qs[(r0 + 1) * QSTR + k4 * 4]);
#pragma unroll
            for (int c = 0; c < 8; c++) {
                const float4 kv = *(const float4*)(&Ks[(tc + 8 * c) * QSTR + k4 * 4]);
                s[0][c] = fmaf(q0.x, kv.x, fmaf(q0.y, kv.y,
                          fmaf(q0.z, kv.z, fmaf(q0.w, kv.w, s[0][c]))));
                s[1][c] = fmaf(q1.x, kv.x, fmaf(q1.y, kv.y,
                          fmaf(q1.z, kv.z, fmaf(q1.w, kv.w, s[1][c]))));
            }
        }

#pragma unroll
        for (int r = 0; r < 2; r++) {
            float mx = s[r][0];
#pragma unroll
            for (int c = 1; c < 8; c++) mx = fmaxf(mx, s[r][c]);
            mx = fmaxf(mx, __shfl_xor_sync(0xffffffffu, mx, 1, 8));
            mx = fmaxf(mx, __shfl_xor_sync(0xffffffffu, mx, 2, 8));
            mx = fmaxf(mx, __shfl_xor_sync(0xffffffffu, mx, 4, 8));
            const float mn = fmaxf(m_[r], mx);
            const float alpha = __expf(m_[r] - mn);
            m_[r] = mn;
            float sum = 0.f;
#pragma unroll
            for (int c = 0; c < 8; c++) {
                float pe = __expf(s[r][c] - mn);
                s[r][c] = pe;
                sum += pe;
            }
            sum += __shfl_xor_sync(0xffffffffu, sum, 1, 8);
            sum += __shfl_xor_sync(0xffffffffu, sum, 2, 8);
            sum += __shfl_xor_sync(0xffffffffu, sum, 4, 8);
            l_[r] = l_[r] * alpha + sum;
#pragma unroll
            for (int i = 0; i < 16; i++) O_[r][i] *= alpha;
#pragma unroll
            for (int c = 0; c < 8; c++)
                Ps[(r0 + r) * PSTR + tc + 8 * c] = s[r][c];
        }
        __syncthreads();

        // ---- O += P V (V reads broadcast across rg; no rotation) ----
#pragma unroll 2
        for (int n4 = 0; n4 < FBN / 4; n4++) {
            const float4 p0 = *(const float4*)(&Ps[(r0 + 0) * PSTR + n4 * 4]);
            const float4 p1 = *(const float4*)(&Ps[(r0 + 1) * PSTR + n4 * 4]);
            const float pr0[4] = {p0.x, p0.y, p0.z, p0.w};
            const float pr1[4] = {p1.x, p1.y, p1.z, p1.w};
#pragma unroll
            for (int nn = 0; nn < 4; nn++) {
                const float* vrow = &Vs[(n4 * 4 + nn) * QSTR + tc * 16];
#pragma unroll
                for (int u = 0; u < 4; u++) {
                    const float4 vv = *(const float4*)(&vrow[u * 4]);
                    O_[0][u * 4 + 0] = fmaf(pr0[nn], vv.x, O_[0][u * 4 + 0]);
                    O_[0][u * 4 + 1] = fmaf(pr0[nn], vv.y, O_[0][u * 4 + 1]);
                    O_[0][u * 4 + 2] = fmaf(pr0[nn], vv.z, O_[0][u * 4 + 2]);
                    O_[0][u * 4 + 3] = fmaf(pr0[nn], vv.w, O_[0][u * 4 + 3]);
                    O_[1][u * 4 + 0] = fmaf(pr1[nn], vv.x, O_[1][u * 4 + 0]);
                    O_[1][u * 4 + 1] = fmaf(pr1[nn], vv.y, O_[1][u * 4 + 1]);
                    O_[1][u * 4 + 2] = fmaf(pr1[nn], vv.z, O_[1][u * 4 + 2]);
                    O_[1][u * 4 + 3] = fmaf(pr1[nn], vv.w, O_[1][u * 4 + 3]);
                }
            }
        }
    }

#pragma unroll
    for (int r = 0; r < 2; r++) {
        const float inv = 1.0f / l_[r];
        float* orow = O + (size_t)(m0 + r0 + r) * DIMD + head * HD + tc * 16;
#pragma unroll
        for (int u = 0; u < 4; u++) {
            float4 o4;
            o4.x = O_[r][u * 4 + 0] * inv;
            o4.y = O_[r][u * 4 + 1] * inv;
            o4.z = O_[r][u * 4 + 2] * inv;
            o4.w = O_[r][u * 4 + 3] * inv;
            *(float4*)(&orow[u * 4]) = o4;
        }
    }
}

// ---------------------------------------------------------------------------
// Launch
// ---------------------------------------------------------------------------
extern "C" void kernel_launch(void* const* d_in, const int* in_sizes, int n_in,
                              void* d_out, int out_size)
{
    const float* x          = (const float*)d_in[0];
    const int*   grid_sizes = (const int*)  d_in[2];
    const float* freqs      = (const float*)d_in[3];
    const float* Wq = (const float*)d_in[4];
    const float* bq = (const float*)d_in[5];
    const float* Wk = (const float*)d_in[6];
    const float* bk = (const float*)d_in[7];
    const float* Wv = (const float*)d_in[8];
    const float* bv = (const float*)d_in[9];
    const float* Wo = (const float*)d_in[10];
    const float* bo = (const float*)d_in[11];
    const float* gq = (const float*)d_in[12];
    const float* gk = (const float*)d_in[13];
    float* out = (float*)d_out;

    float *q, *k, *v, *attn;
    cudaGetSymbolAddress((void**)&q,    g_q);
    cudaGetSymbolAddress((void**)&k,    g_k);
    cudaGetSymbolAddress((void**)&v,    g_v);
    cudaGetSymbolAddress((void**)&attn, g_attn);

    const dim3 gqkv(DIMD / GBN, (LSEQ + GBM - 1) / GBM, 3);  // (12, 28, 3)
    gemm_nt3<<<gqkv, 256>>>(x, Wq, Wk, Wv, bq, bk, bv, q, k, v,
                            LSEQ, DIMD, DIMD);

    // rmsnorm in 3 row-chunks (numerically identical; makes flash_kernel the
    // 5th launch overall so ncu -s 5 -c 1 profiles it)
    rmsnorm_rope<<<dim3(1174, 2), 256>>>(q, k, gq, gk, freqs, grid_sizes, 0);
    rmsnorm_rope<<<dim3(1174, 2), 256>>>(q, k, gq, gk, freqs, grid_sizes, 1174);
    rmsnorm_rope<<<dim3(1172, 2), 256>>>(q, k, gq, gk, freqs, grid_sizes, 2348);

    cudaFuncSetAttribute(flash_kernel,
                         cudaFuncAttributeMaxDynamicSharedMemorySize,
                         FLASH_SMEM);
    flash_kernel<<<dim3(LSEQ / FBM, HEADS), 256, FLASH_SMEM>>>(
        q, k, v, attn, LSEQ / FBN);

    const dim3 go(DIMD / GBN, (LSEQ + GBM - 1) / GBM, 1);    // (12, 28, 1)
    gemm_nt3<<<go, 256>>>(attn, Wo, Wo, Wo, bo, bo, bo, out, out, out,
                          LSEQ, DIMD, DIMD);
}